// round 12
// baseline (speedup 1.0000x reference)
#include <cuda_runtime.h>
#include <cuda_fp16.h>
#include <math.h>
#include <stdint.h>

#define EMB    1024
#define S_LEN  2048
#define BATCH  4
#define NH     16
#define HD     64
#define M_TOTAL (BATCH * S_LEN)   // 8192
#define QKV_LD 3072
#define CS_SCALE 0.1803368801111204f   // (1/8) * log2(e)

__device__ __forceinline__ uint32_t smem_to_u32(const void* p) {
    uint32_t a;
    asm("{ .reg .u64 t; cvta.to.shared.u64 t, %1; cvt.u32.u64 %0, t; }"
        : "=r"(a) : "l"(p));
    return a;
}
__device__ __forceinline__ void cpa16(uint32_t s, const void* g) {
    asm volatile("cp.async.cg.shared.global [%0], [%1], 16;\n" :: "r"(s), "l"(g));
}
__device__ __forceinline__ void ldm_x4(uint32_t& r0, uint32_t& r1, uint32_t& r2,
                                       uint32_t& r3, uint32_t addr) {
    asm volatile("ldmatrix.sync.aligned.m8n8.x4.shared.b16 {%0,%1,%2,%3}, [%4];"
                 : "=r"(r0), "=r"(r1), "=r"(r2), "=r"(r3) : "r"(addr));
}
__device__ __forceinline__ void ldm_x4t(uint32_t& r0, uint32_t& r1, uint32_t& r2,
                                        uint32_t& r3, uint32_t addr) {
    asm volatile("ldmatrix.sync.aligned.m8n8.x4.trans.shared.b16 {%0,%1,%2,%3}, [%4];"
                 : "=r"(r0), "=r"(r1), "=r"(r2), "=r"(r3) : "r"(addr));
}
__device__ __forceinline__ void mma_f16(float& c0, float& c1, float& c2, float& c3,
                                        uint32_t a0, uint32_t a1, uint32_t a2, uint32_t a3,
                                        uint32_t b0, uint32_t b1) {
    asm volatile("mma.sync.aligned.m16n8k16.row.col.f32.f16.f16.f32 "
                 "{%0,%1,%2,%3}, {%4,%5,%6,%7}, {%8,%9}, {%0,%1,%2,%3};"
                 : "+f"(c0), "+f"(c1), "+f"(c2), "+f"(c3)
                 : "r"(a0), "r"(a1), "r"(a2), "r"(a3), "r"(b0), "r"(b1));
}
__device__ __forceinline__ uint32_t ex2h2(uint32_t x) {
    uint32_t r; asm("ex2.approx.f16x2 %0, %1;" : "=r"(r) : "r"(x)); return r;
}
__device__ __forceinline__ uint32_t packh2(float a, float b) {
    __half2 h = __floats2half2_rn(a, b);
    return *(uint32_t*)&h;
}

// ======================= scratch globals ====================================
__device__ __half g_xh[(size_t)M_TOTAL * EMB];
__device__ __half g_WTqkv_h[(size_t)QKV_LD * EMB];
__device__ __half g_WTo_h[(size_t)EMB * EMB];
__device__ float  g_biasqkv[QKV_LD];
__device__ __half g_QKVh[(size_t)M_TOTAL * QKV_LD];
__device__ __half g_Oh[(size_t)M_TOTAL * EMB];

// ======================= conversion kernels =================================
__global__ void conv_f32_f16(const float* __restrict__ in,
                             __half* __restrict__ hi, int n4) {
    int i = blockIdx.x * blockDim.x + threadIdx.x;
    if (i >= n4) return;
    float4 v = ((const float4*)in)[i];
    uint32_t* H = (uint32_t*)hi;
    H[2 * i]     = packh2(v.x, v.y);
    H[2 * i + 1] = packh2(v.z, v.w);
}

// All 4 weight transposes in one launch. Wq (z==0) pre-scaled by CS_SCALE.
__global__ void wsplit_all(const float* __restrict__ W0, const float* __restrict__ W1,
                           const float* __restrict__ W2, const float* __restrict__ W3,
                           __half* __restrict__ dq, __half* __restrict__ dо) {
    const float* Ws[4] = {W0, W1, W2, W3};
    const float* W = Ws[blockIdx.z];
    __half* dst = (blockIdx.z < 3) ? dq + (size_t)blockIdx.z * EMB * EMB : dо;
    const float sc = (blockIdx.z == 0) ? CS_SCALE : 1.0f;
    __shared__ float t[32][33];
    const int n0 = blockIdx.x * 32, k0 = blockIdx.y * 32;
    const int tx = threadIdx.x, ty = threadIdx.y;
    #pragma unroll
    for (int r = 0; r < 32; r += 8)
        t[ty + r][tx] = W[(size_t)(k0 + ty + r) * EMB + n0 + tx];
    __syncthreads();
    #pragma unroll
    for (int r = 0; r < 32; r += 8)
        dst[(size_t)(n0 + ty + r) * EMB + k0 + tx] = __float2half_rn(t[tx][ty + r] * sc);
}

__global__ void concat_bias(const float* __restrict__ bq, const float* __restrict__ bk,
                            const float* __restrict__ bv, float* __restrict__ o) {
    int i = blockIdx.x * blockDim.x + threadIdx.x;
    if (i < EMB) {
        o[i] = bq[i] * CS_SCALE;   // match pre-scaled Wq
        o[EMB + i] = bk[i];
        o[2 * EMB + i] = bv[i];
    }
}

// ================= QKV GEMM: 128x64 tile, warp tile 32x32, 3 CTAs/SM =======
// acc 32 regs/thread -> ~70 total, RF allows 24 warps/SM. Per k16 per warp:
// 8 MMA / 4 LDSM.x4 = 256 B/MMA, co-saturating smem crossbar & tensor pipe.
#define QG_M 128
#define QG_N 64
#define QG_NCH 16
#define QG_STAGE (QG_M * 128 + QG_N * 128)    // A 16KB + B 8KB = 24KB
#define QG_SMEM (3 * QG_STAGE)                // 72KB

__global__ __launch_bounds__(256, 3)
void gemm_qkv(const __half* __restrict__ A, const __half* __restrict__ B,
              const float* __restrict__ bias, __half* __restrict__ Ch) {
    extern __shared__ char smem[];
    const uint32_t sb = smem_to_u32(smem);
    const int tid  = threadIdx.x;
    const int wid  = tid >> 5;
    const int lane = tid & 31;
    const int wm = wid & 3;          // 4 groups x 32 rows
    const int wn = wid >> 2;         // 2 groups x 32 cols
    const int m0 = blockIdx.y * QG_M;
    const int n0 = blockIdx.x * QG_N;

    auto load_chunk = [&](int kc) {
        const uint32_t ab = sb + (kc % 3) * QG_STAGE;
        const uint32_t bb = ab + QG_M * 128;
        #pragma unroll
        for (int j = 0; j < 4; ++j) {           // A: 1024 granules
            const int idx = tid + j * 256;
            const int row = idx >> 3, g = idx & 7;
            const uint32_t off = row * 128 + ((g * 16) ^ ((row & 7) << 4));
            cpa16(ab + off, A + (size_t)(m0 + row) * EMB + kc * 64 + g * 8);
        }
        #pragma unroll
        for (int j = 0; j < 2; ++j) {           // B: 512 granules
            const int idx = tid + j * 256;
            const int row = idx >> 3, g = idx & 7;
            const uint32_t off = row * 128 + ((g * 16) ^ ((row & 7) << 4));
            cpa16(bb + off, B + (size_t)(n0 + row) * EMB + kc * 64 + g * 8);
        }
        asm volatile("cp.async.commit_group;\n" ::: "memory");
    };

    float acc[2][4][4];
    #pragma unroll
    for (int mt = 0; mt < 2; ++mt)
        #pragma unroll
        for (int nt = 0; nt < 4; ++nt)
            #pragma unroll
            for (int r = 0; r < 4; ++r) acc[mt][nt][r] = 0.0f;

    const int a_rl = wm * 32 + (lane & 15);
    const int akb  = (lane >> 4) * 16;
    const int asx  = (a_rl & 7) << 4;
    const int b_rl = wn * 32 + (lane & 7) + ((lane >> 4) & 1) * 8;
    const int bkb  = ((lane >> 3) & 1) * 16;
    const int bsx  = (b_rl & 7) << 4;

    load_chunk(0);
    load_chunk(1);

    for (int i = 0; i < QG_NCH; ++i) {
        if (i + 1 < QG_NCH) asm volatile("cp.async.wait_group 1;\n" ::: "memory");
        else                asm volatile("cp.async.wait_group 0;\n" ::: "memory");
        __syncthreads();

        if (i + 2 < QG_NCH) load_chunk(i + 2);

        const uint32_t ab = sb + (i % 3) * QG_STAGE;
        const uint32_t bb = ab + QG_M * 128;

        #pragma unroll
        for (int k16 = 0; k16 < 4; ++k16) {
            const int kb = k16 * 32;
            uint32_t a[2][4];
            #pragma unroll
            for (int mt = 0; mt < 2; ++mt)
                ldm_x4(a[mt][0], a[mt][1], a[mt][2], a[mt][3],
                       ab + (a_rl + mt * 16) * 128 + ((kb + akb) ^ asx));
            uint32_t b[4][2];
            #pragma unroll
            for (int nt2 = 0; nt2 < 2; ++nt2) {
                uint32_t r0, r1, r2, r3;
                ldm_x4(r0, r1, r2, r3,
                       bb + (b_rl + nt2 * 16) * 128 + ((kb + bkb) ^ bsx));
                b[nt2 * 2][0] = r0; b[nt2 * 2][1] = r1;
                b[nt2 * 2 + 1][0] = r2; b[nt2 * 2 + 1][1] = r3;
            }
            #pragma unroll
            for (int mt = 0; mt < 2; ++mt)
                #pragma unroll
                for (int nt = 0; nt < 4; ++nt)
                    mma_f16(acc[mt][nt][0], acc[mt][nt][1], acc[mt][nt][2], acc[mt][nt][3],
                            a[mt][0], a[mt][1], a[mt][2], a[mt][3],
                            b[nt][0], b[nt][1]);
        }
    }

    const int rbase = m0 + wm * 32 + (lane >> 2);
    const int cbase = n0 + wn * 32 + (lane & 3) * 2;
    #pragma unroll
    for (int mt = 0; mt < 2; ++mt) {
        #pragma unroll
        for (int nt = 0; nt < 4; ++nt) {
            const int c = cbase + nt * 8;
            const float b0 = bias[c], b1 = bias[c + 1];
            const size_t o0 = (size_t)(rbase + mt * 16) * QKV_LD + c;
            const size_t o1 = (size_t)(rbase + mt * 16 + 8) * QKV_LD + c;
            *(uint32_t*)(Ch + o0) = packh2(acc[mt][nt][0] + b0, acc[mt][nt][1] + b1);
            *(uint32_t*)(Ch + o1) = packh2(acc[mt][nt][2] + b0, acc[mt][nt][3] + b1);
        }
    }
}

// ======================= O-proj GEMM (128x128, fp32 out) ====================
#define GT_M 128
#define GT_N 128
#define NCH  16
#define STAGE_BYTES (2 * GT_M * 128)
#define GEMM_SMEM_BYTES (3 * STAGE_BYTES)

__global__ __launch_bounds__(256, 2)
void gemm_f16(const __half* __restrict__ A, const __half* __restrict__ B,
              const float* __restrict__ bias, float* __restrict__ Cf, int ldC) {
    extern __shared__ char smem[];
    const uint32_t sb = smem_to_u32(smem);
    const int tid  = threadIdx.x;
    const int wid  = tid >> 5;
    const int lane = tid & 31;
    const int wm = wid & 1;
    const int wn = wid >> 1;
    const int m0 = blockIdx.y * GT_M;
    const int n0 = blockIdx.x * GT_N;

    auto load_chunk = [&](int kc) {
        const uint32_t ab = sb + (kc % 3) * STAGE_BYTES;
        const uint32_t bb = ab + GT_M * 128;
        #pragma unroll
        for (int j = 0; j < 4; ++j) {
            const int idx = tid + j * 256;
            const int row = idx >> 3, g = idx & 7;
            const uint32_t off = row * 128 + ((g * 16) ^ ((row & 7) << 4));
            cpa16(ab + off, A + (size_t)(m0 + row) * EMB + kc * 64 + g * 8);
        }
        #pragma unroll
        for (int j = 0; j < 4; ++j) {
            const int idx = tid + j * 256;
            const int row = idx >> 3, g = idx & 7;
            const uint32_t off = row * 128 + ((g * 16) ^ ((row & 7) << 4));
            cpa16(bb + off, B + (size_t)(n0 + row) * EMB + kc * 64 + g * 8);
        }
        asm volatile("cp.async.commit_group;\n" ::: "memory");
    };

    float acc[4][4][4];
    #pragma unroll
    for (int mt = 0; mt < 4; ++mt)
        #pragma unroll
        for (int nt = 0; nt < 4; ++nt)
            #pragma unroll
            for (int r = 0; r < 4; ++r) acc[mt][nt][r] = 0.0f;

    const int arow_l  = wm * 64 + (lane & 15);
    const int akb_l   = (lane >> 4) * 16;
    const int asx     = (arow_l & 7) << 4;
    const int brow_l  = wn * 32 + (lane & 7) + ((lane >> 4) & 1) * 8;
    const int bkb_l   = ((lane >> 3) & 1) * 16;
    const int bsx     = (brow_l & 7) << 4;

    load_chunk(0);
    load_chunk(1);

    for (int i = 0; i < NCH; ++i) {
        if (i + 1 < NCH) asm volatile("cp.async.wait_group 1;\n" ::: "memory");
        else             asm volatile("cp.async.wait_group 0;\n" ::: "memory");
        __syncthreads();

        if (i + 2 < NCH) load_chunk(i + 2);

        const uint32_t ab = sb + (i % 3) * STAGE_BYTES;
        const uint32_t bb = ab + GT_M * 128;

        #pragma unroll
        for (int k16 = 0; k16 < 4; ++k16) {
            const int kb = k16 * 32;
            uint32_t a[4][4];
            #pragma unroll
            for (int mt = 0; mt < 4; ++mt) {
                const int row = arow_l + mt * 16;
                ldm_x4(a[mt][0], a[mt][1], a[mt][2], a[mt][3],
                       ab + row * 128 + ((kb + akb_l) ^ asx));
            }
            uint32_t b[4][2];
            #pragma unroll
            for (int nt2 = 0; nt2 < 2; ++nt2) {
                const int row = brow_l + nt2 * 16;
                uint32_t r0, r1, r2, r3;
                ldm_x4(r0, r1, r2, r3, bb + row * 128 + ((kb + bkb_l) ^ bsx));
                b[nt2 * 2][0] = r0; b[nt2 * 2][1] = r1;
                b[nt2 * 2 + 1][0] = r2; b[nt2 * 2 + 1][1] = r3;
            }
            #pragma unroll
            for (int mt = 0; mt < 4; ++mt)
                #pragma unroll
                for (int nt = 0; nt < 4; ++nt)
                    mma_f16(acc[mt][nt][0], acc[mt][nt][1], acc[mt][nt][2], acc[mt][nt][3],
                            a[mt][0], a[mt][1], a[mt][2], a[mt][3],
                            b[nt][0], b[nt][1]);
        }
    }

    const int rbase = m0 + wm * 64 + (lane >> 2);
    const int cbase = n0 + wn * 32 + (lane & 3) * 2;
    #pragma unroll
    for (int mt = 0; mt < 4; ++mt) {
        #pragma unroll
        for (int nt = 0; nt < 4; ++nt) {
            const int c = cbase + nt * 8;
            const float b0 = bias[c], b1 = bias[c + 1];
            float2 v0, v1;
            v0.x = acc[mt][nt][0] + b0; v0.y = acc[mt][nt][1] + b1;
            v1.x = acc[mt][nt][2] + b0; v1.y = acc[mt][nt][3] + b1;
            *(float2*)&Cf[(size_t)(rbase + mt * 16) * ldC + c] = v0;
            *(float2*)&Cf[(size_t)(rbase + mt * 16 + 8) * ldC + c] = v1;
        }
    }
}

// ======================= tensor-core flash attention ========================
// Max-free softmax, Q pre-scaled (P = 2^s), l via ones-MMA, Q frags hoisted.
// smem: Q 16K | 4 stages x (K 8K + V 8K) = 80KB; 2 CTAs/SM.
#define ATT_SMEM 81920
#define ONES_H2 0x3C003C00u

__global__ __launch_bounds__(256, 2)
void attn_mma(const __half* __restrict__ QKV,
              __half* __restrict__ O) {
    extern __shared__ char smem[];
    const uint32_t sb  = smem_to_u32(smem);
    const uint32_t sQ  = sb;
    const uint32_t sKV = sb + 16384;

    const int tid = threadIdx.x, wid = tid >> 5, lane = tid & 31;
    const int bh = blockIdx.y;
    const int b = bh >> 4, h = bh & 15;
    const int qbase = blockIdx.x * 128;
    const size_t rowbase = (size_t)b * S_LEN;

    const __half* q_g = QKV + rowbase * QKV_LD + h * HD;
    const __half* k_g = q_g + EMB;
    const __half* v_g = q_g + 2 * EMB;

    auto ldKV = [&](int t) {
        const uint32_t base = sKV + (t & 3) * 16384;
        #pragma unroll
        for (int j = 0; j < 2; ++j) {
            const int idx = tid + j * 256;
            const int row = idx >> 3, g = idx & 7;
            const uint32_t off = row * 128 + ((g * 16) ^ ((row & 7) << 4));
            const size_t gofs = (size_t)(t * 64 + row) * QKV_LD + g * 8;
            cpa16(base + off,        k_g + gofs);
            cpa16(base + 8192 + off, v_g + gofs);
        }
        asm volatile("cp.async.commit_group;\n" ::: "memory");
    };

    #pragma unroll
    for (int j = 0; j < 4; ++j) {
        const int idx = tid + j * 256;
        const int row = idx >> 3, g = idx & 7;
        const uint32_t off = row * 128 + ((g * 16) ^ ((row & 7) << 4));
        cpa16(sQ + off, q_g + (size_t)(qbase + row) * QKV_LD + g * 8);
    }
    ldKV(0);
    ldKV(1);
    ldKV(2);

    const int wr    = wid * 16;
    const int q_row = wr + (lane & 7) + ((lane >> 3) & 1) * 8;
    const int q_sx  = (q_row & 7) << 4;
    const int q_cb  = ((lane >> 4) & 1) * 16;
    const int k_rl  = (lane & 7) + ((lane >> 4) & 1) * 8;
    const int k_cb  = ((lane >> 3) & 1) * 16;
    const int v_rl  = (lane & 7) + ((lane >> 3) & 1) * 8;
    const int v_cb  = ((lane >> 4) & 1) * 16;

    float lacc[4] = {0.0f, 0.0f, 0.0f, 0.0f};
    float acc[8][4];
    #pragma unroll
    for (int e = 0; e < 8; ++e)
        #pragma unroll
        for (int r = 0; r < 4; ++r) acc[e][r] = 0.0f;

    const int NT = S_LEN / 64;

    asm volatile("cp.async.wait_group 2;\n" ::: "memory");
    __syncthreads();

    uint32_t qf[4][4];
    #pragma unroll
    for (int kd = 0; kd < 4; ++kd)
        ldm_x4(qf[kd][0], qf[kd][1], qf[kd][2], qf[kd][3],
               sQ + q_row * 128 + ((kd * 32 + q_cb) ^ q_sx));

    for (int t = 0; t < NT; ++t) {
        if (t > 0) {
            if (t < NT - 2)       asm volatile("cp.async.wait_group 2;\n" ::: "memory");
            else if (t == NT - 2) asm volatile("cp.async.wait_group 1;\n" ::: "memory");
            else                  asm volatile("cp.async.wait_group 0;\n" ::: "memory");
            __syncthreads();
        }

        if (t + 3 < NT) ldKV(t + 3);

        const uint32_t kb = sKV + (t & 3) * 16384;
        const uint32_t vb = kb + 8192;

        #pragma unroll
        for (int j = 0; j < 4; ++j) {
            float s0[4], s1[4];
            #pragma unroll
            for (int r = 0; r < 4; ++r) { s0[r] = 0.0f; s1[r] = 0.0f; }

            const int krow = j * 16 + k_rl;
            const int ksx  = (krow & 7) << 4;
            #pragma unroll
            for (int kd = 0; kd < 4; ++kd) {
                uint32_t k0, k1, k2, k3;
                ldm_x4(k0, k1, k2, k3,
                       kb + krow * 128 + ((kd * 32 + k_cb) ^ ksx));
                mma_f16(s0[0], s0[1], s0[2], s0[3],
                        qf[kd][0], qf[kd][1], qf[kd][2], qf[kd][3], k0, k1);
                mma_f16(s1[0], s1[1], s1[2], s1[3],
                        qf[kd][0], qf[kd][1], qf[kd][2], qf[kd][3], k2, k3);
            }

            uint32_t ap[4];
            ap[0] = ex2h2(packh2(s0[0], s0[1]));
            ap[1] = ex2h2(packh2(s0[2], s0[3]));
            ap[2] = ex2h2(packh2(s1[0], s1[1]));
            ap[3] = ex2h2(packh2(s1[2], s1[3]));

            mma_f16(lacc[0], lacc[1], lacc[2], lacc[3],
                    ap[0], ap[1], ap[2], ap[3], ONES_H2, ONES_H2);
            const int vrow = j * 16 + v_rl;
            const int vsx  = (vrow & 7) << 4;
            #pragma unroll
            for (int e = 0; e < 4; ++e) {
                uint32_t v0, v1, v2, v3;
                ldm_x4t(v0, v1, v2, v3,
                        vb + vrow * 128 + ((e * 32 + v_cb) ^ vsx));
                mma_f16(acc[2*e][0], acc[2*e][1], acc[2*e][2], acc[2*e][3],
                        ap[0], ap[1], ap[2], ap[3], v0, v1);
                mma_f16(acc[2*e+1][0], acc[2*e+1][1], acc[2*e+1][2], acc[2*e+1][3],
                        ap[0], ap[1], ap[2], ap[3], v2, v3);
            }
        }
        __syncthreads();
    }

    const float inv0 = 1.0f / lacc[0];
    const float inv1 = 1.0f / lacc[2];
    const size_t row0 = rowbase + qbase + wr + (lane >> 2);
    const size_t row1 = row0 + 8;
    const int cb = h * HD + 2 * (lane & 3);
    #pragma unroll
    for (int e = 0; e < 8; ++e) {
        const int c = cb + e * 8;
        *(uint32_t*)(O + row0 * EMB + c) = packh2(acc[e][0] * inv0, acc[e][1] * inv0);
        *(uint32_t*)(O + row1 * EMB + c) = packh2(acc[e][2] * inv1, acc[e][3] * inv1);
    }
}

// ======================= launch =============================================
extern "C" void kernel_launch(void* const* d_in, const int* in_sizes, int n_in,
                              void* d_out, int out_size) {
    const float* x  = (const float*)d_in[0];
    const float* Wq = (const float*)d_in[1];
    const float* bq = (const float*)d_in[2];
    const float* Wk = (const float*)d_in[3];
    const float* bk = (const float*)d_in[4];
    const float* Wv = (const float*)d_in[5];
    const float* bv = (const float*)d_in[6];
    const float* Wo = (const float*)d_in[7];
    const float* bo = (const float*)d_in[8];
    float* out = (float*)d_out;

    __half *xh, *wqh, *woh, *oh, *qkvh;
    float *bqkv;
    cudaGetSymbolAddress((void**)&xh, g_xh);
    cudaGetSymbolAddress((void**)&wqh, g_WTqkv_h);
    cudaGetSymbolAddress((void**)&woh, g_WTo_h);
    cudaGetSymbolAddress((void**)&oh, g_Oh);
    cudaGetSymbolAddress((void**)&qkvh, g_QKVh);
    cudaGetSymbolAddress((void**)&bqkv, g_biasqkv);

    cudaFuncSetAttribute(gemm_qkv, cudaFuncAttributeMaxDynamicSharedMemorySize,
                         QG_SMEM);
    cudaFuncSetAttribute(gemm_f16, cudaFuncAttributeMaxDynamicSharedMemorySize,
                         GEMM_SMEM_BYTES);
    cudaFuncSetAttribute(attn_mma, cudaFuncAttributeMaxDynamicSharedMemorySize,
                         ATT_SMEM);

    const int n4 = M_TOTAL * EMB / 4;
    conv_f32_f16<<<(n4 + 255) / 256, 256>>>(x, xh, n4);
    wsplit_all<<<dim3(32, 32, 4), dim3(32, 8)>>>(Wq, Wk, Wv, Wo, wqh, woh);
    concat_bias<<<4, 256>>>(bq, bk, bv, bqkv);

    // QKV projection (3-CTA/SM tile) -> fp16 QKV
    gemm_qkv<<<dim3(QKV_LD / QG_N, M_TOTAL / QG_M), 256, QG_SMEM>>>(
        xh, wqh, bqkv, qkvh);

    attn_mma<<<dim3(S_LEN / 128, BATCH * NH), 256, ATT_SMEM>>>(qkvh, oh);

    // O-proj -> fp32 out
    gemm_f16<<<dim3(EMB / GT_N, M_TOTAL / GT_M), 256, GEMM_SMEM_BYTES>>>(
        oh, woh, bo, out, EMB);
}

// round 13
// speedup vs baseline: 1.5996x; 1.5996x over previous
#include <cuda_runtime.h>
#include <cuda_fp16.h>
#include <math.h>
#include <stdint.h>

#define EMB    1024
#define S_LEN  2048
#define BATCH  4
#define NH     16
#define HD     64
#define M_TOTAL (BATCH * S_LEN)   // 8192
#define QKV_LD 3072
#define CS_SCALE 0.1803368801111204f   // (1/8) * log2(e)

__device__ __forceinline__ uint32_t smem_to_u32(const void* p) {
    uint32_t a;
    asm("{ .reg .u64 t; cvta.to.shared.u64 t, %1; cvt.u32.u64 %0, t; }"
        : "=r"(a) : "l"(p));
    return a;
}
__device__ __forceinline__ void cpa16(uint32_t s, const void* g) {
    asm volatile("cp.async.cg.shared.global [%0], [%1], 16;\n" :: "r"(s), "l"(g));
}
__device__ __forceinline__ void ldm_x4(uint32_t& r0, uint32_t& r1, uint32_t& r2,
                                       uint32_t& r3, uint32_t addr) {
    asm volatile("ldmatrix.sync.aligned.m8n8.x4.shared.b16 {%0,%1,%2,%3}, [%4];"
                 : "=r"(r0), "=r"(r1), "=r"(r2), "=r"(r3) : "r"(addr));
}
__device__ __forceinline__ void ldm_x4t(uint32_t& r0, uint32_t& r1, uint32_t& r2,
                                        uint32_t& r3, uint32_t addr) {
    asm volatile("ldmatrix.sync.aligned.m8n8.x4.trans.shared.b16 {%0,%1,%2,%3}, [%4];"
                 : "=r"(r0), "=r"(r1), "=r"(r2), "=r"(r3) : "r"(addr));
}
__device__ __forceinline__ void mma_f16(float& c0, float& c1, float& c2, float& c3,
                                        uint32_t a0, uint32_t a1, uint32_t a2, uint32_t a3,
                                        uint32_t b0, uint32_t b1) {
    asm volatile("mma.sync.aligned.m16n8k16.row.col.f32.f16.f16.f32 "
                 "{%0,%1,%2,%3}, {%4,%5,%6,%7}, {%8,%9}, {%0,%1,%2,%3};"
                 : "+f"(c0), "+f"(c1), "+f"(c2), "+f"(c3)
                 : "r"(a0), "r"(a1), "r"(a2), "r"(a3), "r"(b0), "r"(b1));
}
__device__ __forceinline__ uint32_t ex2h2(uint32_t x) {
    uint32_t r; asm("ex2.approx.f16x2 %0, %1;" : "=r"(r) : "r"(x)); return r;
}
__device__ __forceinline__ uint32_t packh2(float a, float b) {
    __half2 h = __floats2half2_rn(a, b);
    return *(uint32_t*)&h;
}

// ======================= scratch globals ====================================
__device__ __half g_xh[(size_t)M_TOTAL * EMB];
__device__ __half g_WTqkv_h[(size_t)QKV_LD * EMB];
__device__ __half g_WTo_h[(size_t)EMB * EMB];
__device__ float  g_biasqkv[QKV_LD];
__device__ __half g_QKVh[(size_t)M_TOTAL * QKV_LD];
__device__ __half g_Oh[(size_t)M_TOTAL * EMB];

// ======================= conversion kernels =================================
__global__ void conv_f32_f16(const float* __restrict__ in,
                             __half* __restrict__ hi, int n4) {
    int i = blockIdx.x * blockDim.x + threadIdx.x;
    if (i >= n4) return;
    float4 v = ((const float4*)in)[i];
    uint32_t* H = (uint32_t*)hi;
    H[2 * i]     = packh2(v.x, v.y);
    H[2 * i + 1] = packh2(v.z, v.w);
}

// All 4 weight transposes in one launch. Wq (z==0) pre-scaled by CS_SCALE.
__global__ void wsplit_all(const float* __restrict__ W0, const float* __restrict__ W1,
                           const float* __restrict__ W2, const float* __restrict__ W3,
                           __half* __restrict__ dq, __half* __restrict__ dо) {
    const float* Ws[4] = {W0, W1, W2, W3};
    const float* W = Ws[blockIdx.z];
    __half* dst = (blockIdx.z < 3) ? dq + (size_t)blockIdx.z * EMB * EMB : dо;
    const float sc = (blockIdx.z == 0) ? CS_SCALE : 1.0f;
    __shared__ float t[32][33];
    const int n0 = blockIdx.x * 32, k0 = blockIdx.y * 32;
    const int tx = threadIdx.x, ty = threadIdx.y;
    #pragma unroll
    for (int r = 0; r < 32; r += 8)
        t[ty + r][tx] = W[(size_t)(k0 + ty + r) * EMB + n0 + tx];
    __syncthreads();
    #pragma unroll
    for (int r = 0; r < 32; r += 8)
        dst[(size_t)(n0 + ty + r) * EMB + k0 + tx] = __float2half_rn(t[tx][ty + r] * sc);
}

__global__ void concat_bias(const float* __restrict__ bq, const float* __restrict__ bk,
                            const float* __restrict__ bv, float* __restrict__ o) {
    int i = blockIdx.x * blockDim.x + threadIdx.x;
    if (i < EMB) {
        o[i] = bq[i] * CS_SCALE;   // match pre-scaled Wq
        o[EMB + i] = bk[i];
        o[2 * EMB + i] = bv[i];
    }
}

// ======================= mma.sync fp16 GEMM (R11 config) ====================
// CTA 128x128, 8 warps, warp tile 64x32 (best LDSM/MMA ratio), 3 stages.
#define GT_M 128
#define GT_N 128
#define NCH  16
#define STAGE_BYTES (2 * GT_M * 128)
#define GEMM_SMEM_BYTES (3 * STAGE_BYTES)

__global__ __launch_bounds__(256, 2)
void gemm_f16(const __half* __restrict__ A, const __half* __restrict__ B,
              const float* __restrict__ bias,
              float* __restrict__ Cf,                 // fp32 out (or null)
              __half* __restrict__ Ch,                // fp16 out
              int ldC) {
    extern __shared__ char smem[];
    const uint32_t sb = smem_to_u32(smem);
    const int tid  = threadIdx.x;
    const int wid  = tid >> 5;
    const int lane = tid & 31;
    const int wm = wid & 1;
    const int wn = wid >> 1;
    const int m0 = blockIdx.y * GT_M;
    const int n0 = blockIdx.x * GT_N;

    auto load_chunk = [&](int kc) {
        const uint32_t ab = sb + (kc % 3) * STAGE_BYTES;
        const uint32_t bb = ab + GT_M * 128;
        #pragma unroll
        for (int j = 0; j < 4; ++j) {
            const int idx = tid + j * 256;
            const int row = idx >> 3, g = idx & 7;
            const uint32_t off = row * 128 + ((g * 16) ^ ((row & 7) << 4));
            cpa16(ab + off, A + (size_t)(m0 + row) * EMB + kc * 64 + g * 8);
        }
        #pragma unroll
        for (int j = 0; j < 4; ++j) {
            const int idx = tid + j * 256;
            const int row = idx >> 3, g = idx & 7;
            const uint32_t off = row * 128 + ((g * 16) ^ ((row & 7) << 4));
            cpa16(bb + off, B + (size_t)(n0 + row) * EMB + kc * 64 + g * 8);
        }
        asm volatile("cp.async.commit_group;\n" ::: "memory");
    };

    float acc[4][4][4];
    #pragma unroll
    for (int mt = 0; mt < 4; ++mt)
        #pragma unroll
        for (int nt = 0; nt < 4; ++nt)
            #pragma unroll
            for (int r = 0; r < 4; ++r) acc[mt][nt][r] = 0.0f;

    const int arow_l  = wm * 64 + (lane & 15);
    const int akb_l   = (lane >> 4) * 16;
    const int asx     = (arow_l & 7) << 4;
    const int brow_l  = wn * 32 + (lane & 7) + ((lane >> 4) & 1) * 8;
    const int bkb_l   = ((lane >> 3) & 1) * 16;
    const int bsx     = (brow_l & 7) << 4;

    load_chunk(0);
    load_chunk(1);

    for (int i = 0; i < NCH; ++i) {
        if (i + 1 < NCH) asm volatile("cp.async.wait_group 1;\n" ::: "memory");
        else             asm volatile("cp.async.wait_group 0;\n" ::: "memory");
        __syncthreads();

        if (i + 2 < NCH) load_chunk(i + 2);

        const uint32_t ab = sb + (i % 3) * STAGE_BYTES;
        const uint32_t bb = ab + GT_M * 128;

        #pragma unroll
        for (int k16 = 0; k16 < 4; ++k16) {
            const int kb = k16 * 32;
            uint32_t a[4][4];
            #pragma unroll
            for (int mt = 0; mt < 4; ++mt) {
                const int row = arow_l + mt * 16;
                ldm_x4(a[mt][0], a[mt][1], a[mt][2], a[mt][3],
                       ab + row * 128 + ((kb + akb_l) ^ asx));
            }
            uint32_t b[4][2];
            #pragma unroll
            for (int nt2 = 0; nt2 < 2; ++nt2) {
                const int row = brow_l + nt2 * 16;
                uint32_t r0, r1, r2, r3;
                ldm_x4(r0, r1, r2, r3, bb + row * 128 + ((kb + bkb_l) ^ bsx));
                b[nt2 * 2][0] = r0; b[nt2 * 2][1] = r1;
                b[nt2 * 2 + 1][0] = r2; b[nt2 * 2 + 1][1] = r3;
            }
            #pragma unroll
            for (int mt = 0; mt < 4; ++mt)
                #pragma unroll
                for (int nt = 0; nt < 4; ++nt)
                    mma_f16(acc[mt][nt][0], acc[mt][nt][1], acc[mt][nt][2], acc[mt][nt][3],
                            a[mt][0], a[mt][1], a[mt][2], a[mt][3],
                            b[nt][0], b[nt][1]);
        }
    }

    const int rbase = m0 + wm * 64 + (lane >> 2);
    const int cbase = n0 + wn * 32 + (lane & 3) * 2;
    if (Cf) {
        #pragma unroll
        for (int mt = 0; mt < 4; ++mt) {
            #pragma unroll
            for (int nt = 0; nt < 4; ++nt) {
                const int c = cbase + nt * 8;
                const float b0 = bias[c], b1 = bias[c + 1];
                float2 v0, v1;
                v0.x = acc[mt][nt][0] + b0; v0.y = acc[mt][nt][1] + b1;
                v1.x = acc[mt][nt][2] + b0; v1.y = acc[mt][nt][3] + b1;
                *(float2*)&Cf[(size_t)(rbase + mt * 16) * ldC + c] = v0;
                *(float2*)&Cf[(size_t)(rbase + mt * 16 + 8) * ldC + c] = v1;
            }
        }
    } else {
        #pragma unroll
        for (int mt = 0; mt < 4; ++mt) {
            #pragma unroll
            for (int nt = 0; nt < 4; ++nt) {
                const int c = cbase + nt * 8;
                const float b0 = bias[c], b1 = bias[c + 1];
                const size_t o0 = (size_t)(rbase + mt * 16) * ldC + c;
                const size_t o1 = (size_t)(rbase + mt * 16 + 8) * ldC + c;
                *(uint32_t*)(Ch + o0) = packh2(acc[mt][nt][0] + b0, acc[mt][nt][1] + b1);
                *(uint32_t*)(Ch + o1) = packh2(acc[mt][nt][2] + b0, acc[mt][nt][3] + b1);
            }
        }
    }
}

// ======================= tensor-core flash attention ========================
// Max-free softmax, Q pre-scaled (P = 2^s), l via ones-MMA, Q frags hoisted.
// ONE barrier per KV tile (top-of-loop, after wait_group): the bottom barrier
// was redundant — the top barrier already orders all readers of stage
// (t+3)&3 = (t-1)&3 before this iteration's ldKV overwrite.
// smem: Q 16K | 4 stages x (K 8K + V 8K) = 80KB; 2 CTAs/SM.
#define ATT_SMEM 81920
#define ONES_H2 0x3C003C00u

__global__ __launch_bounds__(256, 2)
void attn_mma(const __half* __restrict__ QKV,
              __half* __restrict__ O) {
    extern __shared__ char smem[];
    const uint32_t sb  = smem_to_u32(smem);
    const uint32_t sQ  = sb;
    const uint32_t sKV = sb + 16384;

    const int tid = threadIdx.x, wid = tid >> 5, lane = tid & 31;
    const int bh = blockIdx.y;
    const int b = bh >> 4, h = bh & 15;
    const int qbase = blockIdx.x * 128;
    const size_t rowbase = (size_t)b * S_LEN;

    const __half* q_g = QKV + rowbase * QKV_LD + h * HD;
    const __half* k_g = q_g + EMB;
    const __half* v_g = q_g + 2 * EMB;

    auto ldKV = [&](int t) {
        const uint32_t base = sKV + (t & 3) * 16384;
        #pragma unroll
        for (int j = 0; j < 2; ++j) {
            const int idx = tid + j * 256;
            const int row = idx >> 3, g = idx & 7;
            const uint32_t off = row * 128 + ((g * 16) ^ ((row & 7) << 4));
            const size_t gofs = (size_t)(t * 64 + row) * QKV_LD + g * 8;
            cpa16(base + off,        k_g + gofs);
            cpa16(base + 8192 + off, v_g + gofs);
        }
        asm volatile("cp.async.commit_group;\n" ::: "memory");
    };

    #pragma unroll
    for (int j = 0; j < 4; ++j) {
        const int idx = tid + j * 256;
        const int row = idx >> 3, g = idx & 7;
        const uint32_t off = row * 128 + ((g * 16) ^ ((row & 7) << 4));
        cpa16(sQ + off, q_g + (size_t)(qbase + row) * QKV_LD + g * 8);
    }
    ldKV(0);
    ldKV(1);
    ldKV(2);

    const int wr    = wid * 16;
    const int q_row = wr + (lane & 7) + ((lane >> 3) & 1) * 8;
    const int q_sx  = (q_row & 7) << 4;
    const int q_cb  = ((lane >> 4) & 1) * 16;
    const int k_rl  = (lane & 7) + ((lane >> 4) & 1) * 8;
    const int k_cb  = ((lane >> 3) & 1) * 16;
    const int v_rl  = (lane & 7) + ((lane >> 3) & 1) * 8;
    const int v_cb  = ((lane >> 4) & 1) * 16;

    float lacc[4] = {0.0f, 0.0f, 0.0f, 0.0f};
    float acc[8][4];
    #pragma unroll
    for (int e = 0; e < 8; ++e)
        #pragma unroll
        for (int r = 0; r < 4; ++r) acc[e][r] = 0.0f;

    const int NT = S_LEN / 64;

    // prologue: Q + KV0 landed
    asm volatile("cp.async.wait_group 2;\n" ::: "memory");
    __syncthreads();

    // hoist Q fragments (constant over the whole KV loop)
    uint32_t qf[4][4];
    #pragma unroll
    for (int kd = 0; kd < 4; ++kd)
        ldm_x4(qf[kd][0], qf[kd][1], qf[kd][2], qf[kd][3],
               sQ + q_row * 128 + ((kd * 32 + q_cb) ^ q_sx));

    for (int t = 0; t < NT; ++t) {
        if (t > 0) {
            if (t < NT - 2)       asm volatile("cp.async.wait_group 2;\n" ::: "memory");
            else if (t == NT - 2) asm volatile("cp.async.wait_group 1;\n" ::: "memory");
            else                  asm volatile("cp.async.wait_group 0;\n" ::: "memory");
            __syncthreads();   // single barrier: orders stage data + WAR for ldKV below
        }

        if (t + 3 < NT) ldKV(t + 3);

        const uint32_t kb = sKV + (t & 3) * 16384;
        const uint32_t vb = kb + 8192;

        #pragma unroll
        for (int j = 0; j < 4; ++j) {
            float s0[4], s1[4];
            #pragma unroll
            for (int r = 0; r < 4; ++r) { s0[r] = 0.0f; s1[r] = 0.0f; }

            const int krow = j * 16 + k_rl;
            const int ksx  = (krow & 7) << 4;
            #pragma unroll
            for (int kd = 0; kd < 4; ++kd) {
                uint32_t k0, k1, k2, k3;
                ldm_x4(k0, k1, k2, k3,
                       kb + krow * 128 + ((kd * 32 + k_cb) ^ ksx));
                mma_f16(s0[0], s0[1], s0[2], s0[3],
                        qf[kd][0], qf[kd][1], qf[kd][2], qf[kd][3], k0, k1);
                mma_f16(s1[0], s1[1], s1[2], s1[3],
                        qf[kd][0], qf[kd][1], qf[kd][2], qf[kd][3], k2, k3);
            }

            uint32_t ap[4];
            ap[0] = ex2h2(packh2(s0[0], s0[1]));
            ap[1] = ex2h2(packh2(s0[2], s0[3]));
            ap[2] = ex2h2(packh2(s1[0], s1[1]));
            ap[3] = ex2h2(packh2(s1[2], s1[3]));

            mma_f16(lacc[0], lacc[1], lacc[2], lacc[3],
                    ap[0], ap[1], ap[2], ap[3], ONES_H2, ONES_H2);
            const int vrow = j * 16 + v_rl;
            const int vsx  = (vrow & 7) << 4;
            #pragma unroll
            for (int e = 0; e < 4; ++e) {
                uint32_t v0, v1, v2, v3;
                ldm_x4t(v0, v1, v2, v3,
                        vb + vrow * 128 + ((e * 32 + v_cb) ^ vsx));
                mma_f16(acc[2*e][0], acc[2*e][1], acc[2*e][2], acc[2*e][3],
                        ap[0], ap[1], ap[2], ap[3], v0, v1);
                mma_f16(acc[2*e+1][0], acc[2*e+1][1], acc[2*e+1][2], acc[2*e+1][3],
                        ap[0], ap[1], ap[2], ap[3], v2, v3);
            }
        }
        // no bottom barrier: next iteration's top barrier provides the WAR edge
    }

    const float inv0 = 1.0f / lacc[0];
    const float inv1 = 1.0f / lacc[2];
    const size_t row0 = rowbase + qbase + wr + (lane >> 2);
    const size_t row1 = row0 + 8;
    const int cb = h * HD + 2 * (lane & 3);
    #pragma unroll
    for (int e = 0; e < 8; ++e) {
        const int c = cb + e * 8;
        *(uint32_t*)(O + row0 * EMB + c) = packh2(acc[e][0] * inv0, acc[e][1] * inv0);
        *(uint32_t*)(O + row1 * EMB + c) = packh2(acc[e][2] * inv1, acc[e][3] * inv1);
    }
}

// ======================= launch =============================================
extern "C" void kernel_launch(void* const* d_in, const int* in_sizes, int n_in,
                              void* d_out, int out_size) {
    const float* x  = (const float*)d_in[0];
    const float* Wq = (const float*)d_in[1];
    const float* bq = (const float*)d_in[2];
    const float* Wk = (const float*)d_in[3];
    const float* bk = (const float*)d_in[4];
    const float* Wv = (const float*)d_in[5];
    const float* bv = (const float*)d_in[6];
    const float* Wo = (const float*)d_in[7];
    const float* bo = (const float*)d_in[8];
    float* out = (float*)d_out;

    __half *xh, *wqh, *woh, *oh, *qkvh;
    float *bqkv;
    cudaGetSymbolAddress((void**)&xh, g_xh);
    cudaGetSymbolAddress((void**)&wqh, g_WTqkv_h);
    cudaGetSymbolAddress((void**)&woh, g_WTo_h);
    cudaGetSymbolAddress((void**)&oh, g_Oh);
    cudaGetSymbolAddress((void**)&qkvh, g_QKVh);
    cudaGetSymbolAddress((void**)&bqkv, g_biasqkv);

    cudaFuncSetAttribute(gemm_f16, cudaFuncAttributeMaxDynamicSharedMemorySize,
                         GEMM_SMEM_BYTES);
    cudaFuncSetAttribute(attn_mma, cudaFuncAttributeMaxDynamicSharedMemorySize,
                         ATT_SMEM);

    const int n4 = M_TOTAL * EMB / 4;
    conv_f32_f16<<<(n4 + 255) / 256, 256>>>(x, xh, n4);
    wsplit_all<<<dim3(32, 32, 4), dim3(32, 8)>>>(Wq, Wk, Wv, Wo, wqh, woh);
    concat_bias<<<4, 256>>>(bq, bk, bv, bqkv);

    // QKV projection -> fp16 QKV
    gemm_f16<<<dim3(QKV_LD / GT_N, M_TOTAL / GT_M), 256, GEMM_SMEM_BYTES>>>(
        xh, wqh, bqkv, nullptr, qkvh, QKV_LD);

    // tensor-core flash attention -> fp16 O
    attn_mma<<<dim3(S_LEN / 128, BATCH * NH), 256, ATT_SMEM>>>(qkvh, oh);

    // O-proj -> fp32 out
    gemm_f16<<<dim3(EMB / GT_N, M_TOTAL / GT_M), 256, GEMM_SMEM_BYTES>>>(
        oh, woh, bo, out, nullptr, EMB);
}

// round 14
// speedup vs baseline: 1.6363x; 1.0229x over previous
#include <cuda_runtime.h>
#include <cuda_fp16.h>
#include <math.h>
#include <stdint.h>

#define EMB    1024
#define S_LEN  2048
#define BATCH  4
#define NH     16
#define HD     64
#define M_TOTAL (BATCH * S_LEN)   // 8192
#define QKV_LD 3072
#define CS_SCALE 0.1803368801111204f   // (1/8) * log2(e)

__device__ __forceinline__ uint32_t smem_to_u32(const void* p) {
    uint32_t a;
    asm("{ .reg .u64 t; cvta.to.shared.u64 t, %1; cvt.u32.u64 %0, t; }"
        : "=r"(a) : "l"(p));
    return a;
}
__device__ __forceinline__ void cpa16(uint32_t s, const void* g) {
    asm volatile("cp.async.cg.shared.global [%0], [%1], 16;\n" :: "r"(s), "l"(g));
}
__device__ __forceinline__ void ldm_x4(uint32_t& r0, uint32_t& r1, uint32_t& r2,
                                       uint32_t& r3, uint32_t addr) {
    asm volatile("ldmatrix.sync.aligned.m8n8.x4.shared.b16 {%0,%1,%2,%3}, [%4];"
                 : "=r"(r0), "=r"(r1), "=r"(r2), "=r"(r3) : "r"(addr));
}
__device__ __forceinline__ void ldm_x4t(uint32_t& r0, uint32_t& r1, uint32_t& r2,
                                        uint32_t& r3, uint32_t addr) {
    asm volatile("ldmatrix.sync.aligned.m8n8.x4.trans.shared.b16 {%0,%1,%2,%3}, [%4];"
                 : "=r"(r0), "=r"(r1), "=r"(r2), "=r"(r3) : "r"(addr));
}
__device__ __forceinline__ void mma_f16(float& c0, float& c1, float& c2, float& c3,
                                        uint32_t a0, uint32_t a1, uint32_t a2, uint32_t a3,
                                        uint32_t b0, uint32_t b1) {
    asm volatile("mma.sync.aligned.m16n8k16.row.col.f32.f16.f16.f32 "
                 "{%0,%1,%2,%3}, {%4,%5,%6,%7}, {%8,%9}, {%0,%1,%2,%3};"
                 : "+f"(c0), "+f"(c1), "+f"(c2), "+f"(c3)
                 : "r"(a0), "r"(a1), "r"(a2), "r"(a3), "r"(b0), "r"(b1));
}
__device__ __forceinline__ uint32_t ex2h2(uint32_t x) {
    uint32_t r; asm("ex2.approx.f16x2 %0, %1;" : "=r"(r) : "r"(x)); return r;
}
__device__ __forceinline__ uint32_t packh2(float a, float b) {
    __half2 h = __floats2half2_rn(a, b);
    return *(uint32_t*)&h;
}

// ======================= scratch globals ====================================
__device__ __half g_xh[(size_t)M_TOTAL * EMB];
__device__ __half g_WTqkv_h[(size_t)QKV_LD * EMB];
__device__ __half g_WTo_h[(size_t)EMB * EMB];
__device__ float  g_biasqkv[QKV_LD];
__device__ __half g_QKVh[(size_t)M_TOTAL * QKV_LD];
__device__ __half g_Oh[(size_t)M_TOTAL * EMB];

// ======================= fused prep kernel ==================================
// All independent preprocessing in ONE launch, partitioned by blockIdx.x:
//   [0, 4096)    : x fp32 -> fp16 (2 x float4 per thread)
//   [4096, 8192) : 4 weight transposes (Wq pre-scaled by CS_SCALE)
//   [8192, 8196) : bias concat (bq scaled)
// Roles run concurrently across SMs, overlapping their memory latencies.
#define PREP_CONV_BLKS   4096
#define PREP_W_BLKS      4096
#define PREP_GRID        (PREP_CONV_BLKS + PREP_W_BLKS + 4)

__global__ void prep_all(const float* __restrict__ x,
                         const float* __restrict__ W0, const float* __restrict__ W1,
                         const float* __restrict__ W2, const float* __restrict__ W3,
                         const float* __restrict__ bq, const float* __restrict__ bk,
                         const float* __restrict__ bv,
                         __half* __restrict__ xh,
                         __half* __restrict__ dq, __half* __restrict__ dо,
                         float* __restrict__ biasqkv) {
    const int bid = blockIdx.x;
    const int tid = threadIdx.x;

    if (bid < PREP_CONV_BLKS) {
        // ---- x conversion: 512 float4 per block
        const int i0 = bid * 512 + tid;
        uint32_t* H = (uint32_t*)xh;
        #pragma unroll
        for (int u = 0; u < 2; ++u) {
            const int i = i0 + u * 256;
            float4 v = ((const float4*)x)[i];
            H[2 * i]     = packh2(v.x, v.y);
            H[2 * i + 1] = packh2(v.z, v.w);
        }
    } else if (bid < PREP_CONV_BLKS + PREP_W_BLKS) {
        // ---- weight transpose: idx -> (z, n0, k0)
        const int idx = bid - PREP_CONV_BLKS;
        const int z   = idx >> 10;
        const int rem = idx & 1023;
        const int n0  = (rem & 31) * 32;
        const int k0  = (rem >> 5) * 32;
        const float* Ws[4] = {W0, W1, W2, W3};
        const float* W = Ws[z];
        __half* dst = (z < 3) ? dq + (size_t)z * EMB * EMB : dо;
        const float sc = (z == 0) ? CS_SCALE : 1.0f;

        __shared__ float t[32][33];
        const int tx = tid & 31, ty = tid >> 5;
        #pragma unroll
        for (int r = 0; r < 32; r += 8)
            t[ty + r][tx] = W[(size_t)(k0 + ty + r) * EMB + n0 + tx];
        __syncthreads();
        #pragma unroll
        for (int r = 0; r < 32; r += 8)
            dst[(size_t)(n0 + ty + r) * EMB + k0 + tx] = __float2half_rn(t[tx][ty + r] * sc);
    } else {
        // ---- bias concat
        const int i = (bid - PREP_CONV_BLKS - PREP_W_BLKS) * 256 + tid;
        if (i < EMB) {
            biasqkv[i] = bq[i] * CS_SCALE;
            biasqkv[EMB + i] = bk[i];
            biasqkv[2 * EMB + i] = bv[i];
        }
    }
}

// ======================= mma.sync fp16 GEMM (R11 config) ====================
#define GT_M 128
#define GT_N 128
#define NCH  16
#define STAGE_BYTES (2 * GT_M * 128)
#define GEMM_SMEM_BYTES (3 * STAGE_BYTES)

__global__ __launch_bounds__(256, 2)
void gemm_f16(const __half* __restrict__ A, const __half* __restrict__ B,
              const float* __restrict__ bias,
              float* __restrict__ Cf,                 // fp32 out (or null)
              __half* __restrict__ Ch,                // fp16 out
              int ldC) {
    extern __shared__ char smem[];
    const uint32_t sb = smem_to_u32(smem);
    const int tid  = threadIdx.x;
    const int wid  = tid >> 5;
    const int lane = tid & 31;
    const int wm = wid & 1;
    const int wn = wid >> 1;
    const int m0 = blockIdx.y * GT_M;
    const int n0 = blockIdx.x * GT_N;

    auto load_chunk = [&](int kc) {
        const uint32_t ab = sb + (kc % 3) * STAGE_BYTES;
        const uint32_t bb = ab + GT_M * 128;
        #pragma unroll
        for (int j = 0; j < 4; ++j) {
            const int idx = tid + j * 256;
            const int row = idx >> 3, g = idx & 7;
            const uint32_t off = row * 128 + ((g * 16) ^ ((row & 7) << 4));
            cpa16(ab + off, A + (size_t)(m0 + row) * EMB + kc * 64 + g * 8);
        }
        #pragma unroll
        for (int j = 0; j < 4; ++j) {
            const int idx = tid + j * 256;
            const int row = idx >> 3, g = idx & 7;
            const uint32_t off = row * 128 + ((g * 16) ^ ((row & 7) << 4));
            cpa16(bb + off, B + (size_t)(n0 + row) * EMB + kc * 64 + g * 8);
        }
        asm volatile("cp.async.commit_group;\n" ::: "memory");
    };

    float acc[4][4][4];
    #pragma unroll
    for (int mt = 0; mt < 4; ++mt)
        #pragma unroll
        for (int nt = 0; nt < 4; ++nt)
            #pragma unroll
            for (int r = 0; r < 4; ++r) acc[mt][nt][r] = 0.0f;

    const int arow_l  = wm * 64 + (lane & 15);
    const int akb_l   = (lane >> 4) * 16;
    const int asx     = (arow_l & 7) << 4;
    const int brow_l  = wn * 32 + (lane & 7) + ((lane >> 4) & 1) * 8;
    const int bkb_l   = ((lane >> 3) & 1) * 16;
    const int bsx     = (brow_l & 7) << 4;

    load_chunk(0);
    load_chunk(1);

    for (int i = 0; i < NCH; ++i) {
        if (i + 1 < NCH) asm volatile("cp.async.wait_group 1;\n" ::: "memory");
        else             asm volatile("cp.async.wait_group 0;\n" ::: "memory");
        __syncthreads();

        if (i + 2 < NCH) load_chunk(i + 2);

        const uint32_t ab = sb + (i % 3) * STAGE_BYTES;
        const uint32_t bb = ab + GT_M * 128;

        #pragma unroll
        for (int k16 = 0; k16 < 4; ++k16) {
            const int kb = k16 * 32;
            uint32_t a[4][4];
            #pragma unroll
            for (int mt = 0; mt < 4; ++mt) {
                const int row = arow_l + mt * 16;
                ldm_x4(a[mt][0], a[mt][1], a[mt][2], a[mt][3],
                       ab + row * 128 + ((kb + akb_l) ^ asx));
            }
            uint32_t b[4][2];
            #pragma unroll
            for (int nt2 = 0; nt2 < 2; ++nt2) {
                const int row = brow_l + nt2 * 16;
                uint32_t r0, r1, r2, r3;
                ldm_x4(r0, r1, r2, r3, bb + row * 128 + ((kb + bkb_l) ^ bsx));
                b[nt2 * 2][0] = r0; b[nt2 * 2][1] = r1;
                b[nt2 * 2 + 1][0] = r2; b[nt2 * 2 + 1][1] = r3;
            }
            #pragma unroll
            for (int mt = 0; mt < 4; ++mt)
                #pragma unroll
                for (int nt = 0; nt < 4; ++nt)
                    mma_f16(acc[mt][nt][0], acc[mt][nt][1], acc[mt][nt][2], acc[mt][nt][3],
                            a[mt][0], a[mt][1], a[mt][2], a[mt][3],
                            b[nt][0], b[nt][1]);
        }
    }

    const int rbase = m0 + wm * 64 + (lane >> 2);
    const int cbase = n0 + wn * 32 + (lane & 3) * 2;
    if (Cf) {
        #pragma unroll
        for (int mt = 0; mt < 4; ++mt) {
            #pragma unroll
            for (int nt = 0; nt < 4; ++nt) {
                const int c = cbase + nt * 8;
                const float b0 = bias[c], b1 = bias[c + 1];
                float2 v0, v1;
                v0.x = acc[mt][nt][0] + b0; v0.y = acc[mt][nt][1] + b1;
                v1.x = acc[mt][nt][2] + b0; v1.y = acc[mt][nt][3] + b1;
                *(float2*)&Cf[(size_t)(rbase + mt * 16) * ldC + c] = v0;
                *(float2*)&Cf[(size_t)(rbase + mt * 16 + 8) * ldC + c] = v1;
            }
        }
    } else {
        #pragma unroll
        for (int mt = 0; mt < 4; ++mt) {
            #pragma unroll
            for (int nt = 0; nt < 4; ++nt) {
                const int c = cbase + nt * 8;
                const float b0 = bias[c], b1 = bias[c + 1];
                const size_t o0 = (size_t)(rbase + mt * 16) * ldC + c;
                const size_t o1 = (size_t)(rbase + mt * 16 + 8) * ldC + c;
                *(uint32_t*)(Ch + o0) = packh2(acc[mt][nt][0] + b0, acc[mt][nt][1] + b1);
                *(uint32_t*)(Ch + o1) = packh2(acc[mt][nt][2] + b0, acc[mt][nt][3] + b1);
            }
        }
    }
}

// ======================= tensor-core flash attention ========================
// Max-free softmax, Q pre-scaled (P = 2^s), l via ones-MMA, Q frags hoisted,
// single barrier per KV tile. smem: Q 16K | 4 x (K 8K + V 8K) = 80KB; 2/SM.
#define ATT_SMEM 81920
#define ONES_H2 0x3C003C00u

__global__ __launch_bounds__(256, 2)
void attn_mma(const __half* __restrict__ QKV,
              __half* __restrict__ O) {
    extern __shared__ char smem[];
    const uint32_t sb  = smem_to_u32(smem);
    const uint32_t sQ  = sb;
    const uint32_t sKV = sb + 16384;

    const int tid = threadIdx.x, wid = tid >> 5, lane = tid & 31;
    const int bh = blockIdx.y;
    const int b = bh >> 4, h = bh & 15;
    const int qbase = blockIdx.x * 128;
    const size_t rowbase = (size_t)b * S_LEN;

    const __half* q_g = QKV + rowbase * QKV_LD + h * HD;
    const __half* k_g = q_g + EMB;
    const __half* v_g = q_g + 2 * EMB;

    auto ldKV = [&](int t) {
        const uint32_t base = sKV + (t & 3) * 16384;
        #pragma unroll
        for (int j = 0; j < 2; ++j) {
            const int idx = tid + j * 256;
            const int row = idx >> 3, g = idx & 7;
            const uint32_t off = row * 128 + ((g * 16) ^ ((row & 7) << 4));
            const size_t gofs = (size_t)(t * 64 + row) * QKV_LD + g * 8;
            cpa16(base + off,        k_g + gofs);
            cpa16(base + 8192 + off, v_g + gofs);
        }
        asm volatile("cp.async.commit_group;\n" ::: "memory");
    };

    #pragma unroll
    for (int j = 0; j < 4; ++j) {
        const int idx = tid + j * 256;
        const int row = idx >> 3, g = idx & 7;
        const uint32_t off = row * 128 + ((g * 16) ^ ((row & 7) << 4));
        cpa16(sQ + off, q_g + (size_t)(qbase + row) * QKV_LD + g * 8);
    }
    ldKV(0);
    ldKV(1);
    ldKV(2);

    const int wr    = wid * 16;
    const int q_row = wr + (lane & 7) + ((lane >> 3) & 1) * 8;
    const int q_sx  = (q_row & 7) << 4;
    const int q_cb  = ((lane >> 4) & 1) * 16;
    const int k_rl  = (lane & 7) + ((lane >> 4) & 1) * 8;
    const int k_cb  = ((lane >> 3) & 1) * 16;
    const int v_rl  = (lane & 7) + ((lane >> 3) & 1) * 8;
    const int v_cb  = ((lane >> 4) & 1) * 16;

    float lacc[4] = {0.0f, 0.0f, 0.0f, 0.0f};
    float acc[8][4];
    #pragma unroll
    for (int e = 0; e < 8; ++e)
        #pragma unroll
        for (int r = 0; r < 4; ++r) acc[e][r] = 0.0f;

    const int NT = S_LEN / 64;

    asm volatile("cp.async.wait_group 2;\n" ::: "memory");
    __syncthreads();

    uint32_t qf[4][4];
    #pragma unroll
    for (int kd = 0; kd < 4; ++kd)
        ldm_x4(qf[kd][0], qf[kd][1], qf[kd][2], qf[kd][3],
               sQ + q_row * 128 + ((kd * 32 + q_cb) ^ q_sx));

    for (int t = 0; t < NT; ++t) {
        if (t > 0) {
            if (t < NT - 2)       asm volatile("cp.async.wait_group 2;\n" ::: "memory");
            else if (t == NT - 2) asm volatile("cp.async.wait_group 1;\n" ::: "memory");
            else                  asm volatile("cp.async.wait_group 0;\n" ::: "memory");
            __syncthreads();
        }

        if (t + 3 < NT) ldKV(t + 3);

        const uint32_t kb = sKV + (t & 3) * 16384;
        const uint32_t vb = kb + 8192;

        #pragma unroll
        for (int j = 0; j < 4; ++j) {
            float s0[4], s1[4];
            #pragma unroll
            for (int r = 0; r < 4; ++r) { s0[r] = 0.0f; s1[r] = 0.0f; }

            const int krow = j * 16 + k_rl;
            const int ksx  = (krow & 7) << 4;
            #pragma unroll
            for (int kd = 0; kd < 4; ++kd) {
                uint32_t k0, k1, k2, k3;
                ldm_x4(k0, k1, k2, k3,
                       kb + krow * 128 + ((kd * 32 + k_cb) ^ ksx));
                mma_f16(s0[0], s0[1], s0[2], s0[3],
                        qf[kd][0], qf[kd][1], qf[kd][2], qf[kd][3], k0, k1);
                mma_f16(s1[0], s1[1], s1[2], s1[3],
                        qf[kd][0], qf[kd][1], qf[kd][2], qf[kd][3], k2, k3);
            }

            uint32_t ap[4];
            ap[0] = ex2h2(packh2(s0[0], s0[1]));
            ap[1] = ex2h2(packh2(s0[2], s0[3]));
            ap[2] = ex2h2(packh2(s1[0], s1[1]));
            ap[3] = ex2h2(packh2(s1[2], s1[3]));

            mma_f16(lacc[0], lacc[1], lacc[2], lacc[3],
                    ap[0], ap[1], ap[2], ap[3], ONES_H2, ONES_H2);
            const int vrow = j * 16 + v_rl;
            const int vsx  = (vrow & 7) << 4;
            #pragma unroll
            for (int e = 0; e < 4; ++e) {
                uint32_t v0, v1, v2, v3;
                ldm_x4t(v0, v1, v2, v3,
                        vb + vrow * 128 + ((e * 32 + v_cb) ^ vsx));
                mma_f16(acc[2*e][0], acc[2*e][1], acc[2*e][2], acc[2*e][3],
                        ap[0], ap[1], ap[2], ap[3], v0, v1);
                mma_f16(acc[2*e+1][0], acc[2*e+1][1], acc[2*e+1][2], acc[2*e+1][3],
                        ap[0], ap[1], ap[2], ap[3], v2, v3);
            }
        }
    }

    const float inv0 = 1.0f / lacc[0];
    const float inv1 = 1.0f / lacc[2];
    const size_t row0 = rowbase + qbase + wr + (lane >> 2);
    const size_t row1 = row0 + 8;
    const int cb = h * HD + 2 * (lane & 3);
    #pragma unroll
    for (int e = 0; e < 8; ++e) {
        const int c = cb + e * 8;
        *(uint32_t*)(O + row0 * EMB + c) = packh2(acc[e][0] * inv0, acc[e][1] * inv0);
        *(uint32_t*)(O + row1 * EMB + c) = packh2(acc[e][2] * inv1, acc[e][3] * inv1);
    }
}

// ======================= launch =============================================
extern "C" void kernel_launch(void* const* d_in, const int* in_sizes, int n_in,
                              void* d_out, int out_size) {
    const float* x  = (const float*)d_in[0];
    const float* Wq = (const float*)d_in[1];
    const float* bq = (const float*)d_in[2];
    const float* Wk = (const float*)d_in[3];
    const float* bk = (const float*)d_in[4];
    const float* Wv = (const float*)d_in[5];
    const float* bv = (const float*)d_in[6];
    const float* Wo = (const float*)d_in[7];
    const float* bo = (const float*)d_in[8];
    float* out = (float*)d_out;

    __half *xh, *wqh, *woh, *oh, *qkvh;
    float *bqkv;
    cudaGetSymbolAddress((void**)&xh, g_xh);
    cudaGetSymbolAddress((void**)&wqh, g_WTqkv_h);
    cudaGetSymbolAddress((void**)&woh, g_WTo_h);
    cudaGetSymbolAddress((void**)&oh, g_Oh);
    cudaGetSymbolAddress((void**)&qkvh, g_QKVh);
    cudaGetSymbolAddress((void**)&bqkv, g_biasqkv);

    cudaFuncSetAttribute(gemm_f16, cudaFuncAttributeMaxDynamicSharedMemorySize,
                         GEMM_SMEM_BYTES);
    cudaFuncSetAttribute(attn_mma, cudaFuncAttributeMaxDynamicSharedMemorySize,
                         ATT_SMEM);

    // all preprocessing in one launch (roles overlap across SMs)
    prep_all<<<PREP_GRID, 256>>>(x, Wq, Wk, Wv, Wo, bq, bk, bv,
                                 xh, wqh, woh, bqkv);

    // QKV projection -> fp16 QKV
    gemm_f16<<<dim3(QKV_LD / GT_N, M_TOTAL / GT_M), 256, GEMM_SMEM_BYTES>>>(
        xh, wqh, bqkv, nullptr, qkvh, QKV_LD);

    // tensor-core flash attention -> fp16 O
    attn_mma<<<dim3(S_LEN / 128, BATCH * NH), 256, ATT_SMEM>>>(qkvh, oh);

    // O-proj -> fp32 out
    gemm_f16<<<dim3(EMB / GT_N, M_TOTAL / GT_M), 256, GEMM_SMEM_BYTES>>>(
        oh, woh, bo, out, nullptr, EMB);
}

// round 15
// speedup vs baseline: 1.7442x; 1.0660x over previous
#include <cuda_runtime.h>
#include <cuda_fp16.h>
#include <math.h>
#include <stdint.h>

#define EMB    1024
#define S_LEN  2048
#define BATCH  4
#define NH     16
#define HD     64
#define M_TOTAL (BATCH * S_LEN)   // 8192
#define QKV_LD 3072
#define CS_SCALE 0.1803368801111204f   // (1/8) * log2(e)

__device__ __forceinline__ uint32_t smem_to_u32(const void* p) {
    uint32_t a;
    asm("{ .reg .u64 t; cvta.to.shared.u64 t, %1; cvt.u32.u64 %0, t; }"
        : "=r"(a) : "l"(p));
    return a;
}
__device__ __forceinline__ void cpa16(uint32_t s, const void* g) {
    asm volatile("cp.async.cg.shared.global [%0], [%1], 16;\n" :: "r"(s), "l"(g));
}
__device__ __forceinline__ void ldm_x4(uint32_t& r0, uint32_t& r1, uint32_t& r2,
                                       uint32_t& r3, uint32_t addr) {
    asm volatile("ldmatrix.sync.aligned.m8n8.x4.shared.b16 {%0,%1,%2,%3}, [%4];"
                 : "=r"(r0), "=r"(r1), "=r"(r2), "=r"(r3) : "r"(addr));
}
__device__ __forceinline__ void ldm_x4t(uint32_t& r0, uint32_t& r1, uint32_t& r2,
                                        uint32_t& r3, uint32_t addr) {
    asm volatile("ldmatrix.sync.aligned.m8n8.x4.trans.shared.b16 {%0,%1,%2,%3}, [%4];"
                 : "=r"(r0), "=r"(r1), "=r"(r2), "=r"(r3) : "r"(addr));
}
__device__ __forceinline__ void mma_f16(float& c0, float& c1, float& c2, float& c3,
                                        uint32_t a0, uint32_t a1, uint32_t a2, uint32_t a3,
                                        uint32_t b0, uint32_t b1) {
    asm volatile("mma.sync.aligned.m16n8k16.row.col.f32.f16.f16.f32 "
                 "{%0,%1,%2,%3}, {%4,%5,%6,%7}, {%8,%9}, {%0,%1,%2,%3};"
                 : "+f"(c0), "+f"(c1), "+f"(c2), "+f"(c3)
                 : "r"(a0), "r"(a1), "r"(a2), "r"(a3), "r"(b0), "r"(b1));
}
__device__ __forceinline__ uint32_t ex2h2(uint32_t x) {
    uint32_t r; asm("ex2.approx.f16x2 %0, %1;" : "=r"(r) : "r"(x)); return r;
}
__device__ __forceinline__ uint32_t packh2(float a, float b) {
    __half2 h = __floats2half2_rn(a, b);
    return *(uint32_t*)&h;
}

// ======================= scratch globals ====================================
__device__ __half g_xh[(size_t)M_TOTAL * EMB];
__device__ __half g_WTqkv_h[(size_t)QKV_LD * EMB];
__device__ __half g_WTo_h[(size_t)EMB * EMB];
__device__ float  g_biasqkv[QKV_LD];
__device__ __half g_QKVh[(size_t)M_TOTAL * QKV_LD];
__device__ __half g_Oh[(size_t)M_TOTAL * EMB];
// producer->consumer flags (zeroed by prep_all every launch)
__device__ int g_qkv_done[BATCH * 24];   // [b][nblk]: ==16 when batch b, col-block nblk ready
__device__ int g_attn_done[64];          // [rowblock]: ==16 when all heads of 128-row block done

// ======================= fused prep kernel ==================================
#define PREP_CONV_BLKS   4096
#define PREP_W_BLKS      4096
#define PREP_GRID        (PREP_CONV_BLKS + PREP_W_BLKS + 4)

__global__ void prep_all(const float* __restrict__ x,
                         const float* __restrict__ W0, const float* __restrict__ W1,
                         const float* __restrict__ W2, const float* __restrict__ W3,
                         const float* __restrict__ bq, const float* __restrict__ bk,
                         const float* __restrict__ bv,
                         __half* __restrict__ xh,
                         __half* __restrict__ dq, __half* __restrict__ dо,
                         float* __restrict__ biasqkv) {
    const int bid = blockIdx.x;
    const int tid = threadIdx.x;

    if (bid < PREP_CONV_BLKS) {
        const int i0 = bid * 512 + tid;
        uint32_t* H = (uint32_t*)xh;
        #pragma unroll
        for (int u = 0; u < 2; ++u) {
            const int i = i0 + u * 256;
            float4 v = ((const float4*)x)[i];
            H[2 * i]     = packh2(v.x, v.y);
            H[2 * i + 1] = packh2(v.z, v.w);
        }
    } else if (bid < PREP_CONV_BLKS + PREP_W_BLKS) {
        const int idx = bid - PREP_CONV_BLKS;
        const int z   = idx >> 10;
        const int rem = idx & 1023;
        const int n0  = (rem & 31) * 32;
        const int k0  = (rem >> 5) * 32;
        const float* Ws[4] = {W0, W1, W2, W3};
        const float* W = Ws[z];
        __half* dst = (z < 3) ? dq + (size_t)z * EMB * EMB : dо;
        const float sc = (z == 0) ? CS_SCALE : 1.0f;

        __shared__ float t[32][33];
        const int tx = tid & 31, ty = tid >> 5;
        #pragma unroll
        for (int r = 0; r < 32; r += 8)
            t[ty + r][tx] = W[(size_t)(k0 + ty + r) * EMB + n0 + tx];
        __syncthreads();
        #pragma unroll
        for (int r = 0; r < 32; r += 8)
            dst[(size_t)(n0 + ty + r) * EMB + k0 + tx] = __float2half_rn(t[tx][ty + r] * sc);
    } else {
        const int blk = bid - PREP_CONV_BLKS - PREP_W_BLKS;
        const int i = blk * 256 + tid;
        if (i < EMB) {
            biasqkv[i] = bq[i] * CS_SCALE;
            biasqkv[EMB + i] = bk[i];
            biasqkv[2 * EMB + i] = bv[i];
        }
        if (blk == 0) {   // zero dependency counters
            if (tid < BATCH * 24) g_qkv_done[tid] = 0;
            else if (tid < BATCH * 24 + 64) g_attn_done[tid - BATCH * 24] = 0;
        }
    }
}

// ======================= spin-wait helper ===================================
__device__ __forceinline__ void wait_cnt16(int* p) {
    while (atomicAdd(p, 0) < 16) __nanosleep(128);
}

// ======================= GEMM body (device fn) ==============================
#define GT_M 128
#define GT_N 128
#define NCH  16
#define STAGE_BYTES (2 * GT_M * 128)
#define GEMM_SMEM_BYTES (3 * STAGE_BYTES)   // 96KB

__device__ __forceinline__
void gemm_body(const __half* __restrict__ A, const __half* __restrict__ B,
               const float* __restrict__ bias,
               float* __restrict__ Cf, __half* __restrict__ Ch,
               int ldC, int m0, int n0, char* smem) {
    const uint32_t sb = smem_to_u32(smem);
    const int tid  = threadIdx.x;
    const int wid  = tid >> 5;
    const int lane = tid & 31;
    const int wm = wid & 1;
    const int wn = wid >> 1;

    auto load_chunk = [&](int kc) {
        const uint32_t ab = sb + (kc % 3) * STAGE_BYTES;
        const uint32_t bb = ab + GT_M * 128;
        #pragma unroll
        for (int j = 0; j < 4; ++j) {
            const int idx = tid + j * 256;
            const int row = idx >> 3, g = idx & 7;
            const uint32_t off = row * 128 + ((g * 16) ^ ((row & 7) << 4));
            cpa16(ab + off, A + (size_t)(m0 + row) * EMB + kc * 64 + g * 8);
        }
        #pragma unroll
        for (int j = 0; j < 4; ++j) {
            const int idx = tid + j * 256;
            const int row = idx >> 3, g = idx & 7;
            const uint32_t off = row * 128 + ((g * 16) ^ ((row & 7) << 4));
            cpa16(bb + off, B + (size_t)(n0 + row) * EMB + kc * 64 + g * 8);
        }
        asm volatile("cp.async.commit_group;\n" ::: "memory");
    };

    float acc[4][4][4];
    #pragma unroll
    for (int mt = 0; mt < 4; ++mt)
        #pragma unroll
        for (int nt = 0; nt < 4; ++nt)
            #pragma unroll
            for (int r = 0; r < 4; ++r) acc[mt][nt][r] = 0.0f;

    const int arow_l  = wm * 64 + (lane & 15);
    const int akb_l   = (lane >> 4) * 16;
    const int asx     = (arow_l & 7) << 4;
    const int brow_l  = wn * 32 + (lane & 7) + ((lane >> 4) & 1) * 8;
    const int bkb_l   = ((lane >> 3) & 1) * 16;
    const int bsx     = (brow_l & 7) << 4;

    load_chunk(0);
    load_chunk(1);

    for (int i = 0; i < NCH; ++i) {
        if (i + 1 < NCH) asm volatile("cp.async.wait_group 1;\n" ::: "memory");
        else             asm volatile("cp.async.wait_group 0;\n" ::: "memory");
        __syncthreads();

        if (i + 2 < NCH) load_chunk(i + 2);

        const uint32_t ab = sb + (i % 3) * STAGE_BYTES;
        const uint32_t bb = ab + GT_M * 128;

        #pragma unroll
        for (int k16 = 0; k16 < 4; ++k16) {
            const int kb = k16 * 32;
            uint32_t a[4][4];
            #pragma unroll
            for (int mt = 0; mt < 4; ++mt) {
                const int row = arow_l + mt * 16;
                ldm_x4(a[mt][0], a[mt][1], a[mt][2], a[mt][3],
                       ab + row * 128 + ((kb + akb_l) ^ asx));
            }
            uint32_t b[4][2];
            #pragma unroll
            for (int nt2 = 0; nt2 < 2; ++nt2) {
                const int row = brow_l + nt2 * 16;
                uint32_t r0, r1, r2, r3;
                ldm_x4(r0, r1, r2, r3, bb + row * 128 + ((kb + bkb_l) ^ bsx));
                b[nt2 * 2][0] = r0; b[nt2 * 2][1] = r1;
                b[nt2 * 2 + 1][0] = r2; b[nt2 * 2 + 1][1] = r3;
            }
            #pragma unroll
            for (int mt = 0; mt < 4; ++mt)
                #pragma unroll
                for (int nt = 0; nt < 4; ++nt)
                    mma_f16(acc[mt][nt][0], acc[mt][nt][1], acc[mt][nt][2], acc[mt][nt][3],
                            a[mt][0], a[mt][1], a[mt][2], a[mt][3],
                            b[nt][0], b[nt][1]);
        }
    }

    const int rbase = m0 + wm * 64 + (lane >> 2);
    const int cbase = n0 + wn * 32 + (lane & 3) * 2;
    if (Cf) {
        #pragma unroll
        for (int mt = 0; mt < 4; ++mt) {
            #pragma unroll
            for (int nt = 0; nt < 4; ++nt) {
                const int c = cbase + nt * 8;
                const float b0 = bias[c], b1 = bias[c + 1];
                float2 v0, v1;
                v0.x = acc[mt][nt][0] + b0; v0.y = acc[mt][nt][1] + b1;
                v1.x = acc[mt][nt][2] + b0; v1.y = acc[mt][nt][3] + b1;
                *(float2*)&Cf[(size_t)(rbase + mt * 16) * ldC + c] = v0;
                *(float2*)&Cf[(size_t)(rbase + mt * 16 + 8) * ldC + c] = v1;
            }
        }
    } else {
        #pragma unroll
        for (int mt = 0; mt < 4; ++mt) {
            #pragma unroll
            for (int nt = 0; nt < 4; ++nt) {
                const int c = cbase + nt * 8;
                const float b0 = bias[c], b1 = bias[c + 1];
                const size_t o0 = (size_t)(rbase + mt * 16) * ldC + c;
                const size_t o1 = (size_t)(rbase + mt * 16 + 8) * ldC + c;
                *(uint32_t*)(Ch + o0) = packh2(acc[mt][nt][0] + b0, acc[mt][nt][1] + b1);
                *(uint32_t*)(Ch + o1) = packh2(acc[mt][nt][2] + b0, acc[mt][nt][3] + b1);
            }
        }
    }
}

// ======================= attention body (device fn) =========================
#define ONES_H2 0x3C003C00u

__device__ __forceinline__
void attn_body(const __half* __restrict__ QKV, __half* __restrict__ O,
               int qtile, int bh, char* smem) {
    const uint32_t sb  = smem_to_u32(smem);
    const uint32_t sQ  = sb;
    const uint32_t sKV = sb + 16384;

    const int tid = threadIdx.x, wid = tid >> 5, lane = tid & 31;
    const int b = bh >> 4, h = bh & 15;
    const int qbase = qtile * 128;
    const size_t rowbase = (size_t)b * S_LEN;

    const __half* q_g = QKV + rowbase * QKV_LD + h * HD;
    const __half* k_g = q_g + EMB;
    const __half* v_g = q_g + 2 * EMB;

    auto ldKV = [&](int t) {
        const uint32_t base = sKV + (t & 3) * 16384;
        #pragma unroll
        for (int j = 0; j < 2; ++j) {
            const int idx = tid + j * 256;
            const int row = idx >> 3, g = idx & 7;
            const uint32_t off = row * 128 + ((g * 16) ^ ((row & 7) << 4));
            const size_t gofs = (size_t)(t * 64 + row) * QKV_LD + g * 8;
            cpa16(base + off,        k_g + gofs);
            cpa16(base + 8192 + off, v_g + gofs);
        }
        asm volatile("cp.async.commit_group;\n" ::: "memory");
    };

    #pragma unroll
    for (int j = 0; j < 4; ++j) {
        const int idx = tid + j * 256;
        const int row = idx >> 3, g = idx & 7;
        const uint32_t off = row * 128 + ((g * 16) ^ ((row & 7) << 4));
        cpa16(sQ + off, q_g + (size_t)(qbase + row) * QKV_LD + g * 8);
    }
    ldKV(0);
    ldKV(1);
    ldKV(2);

    const int wr    = wid * 16;
    const int q_row = wr + (lane & 7) + ((lane >> 3) & 1) * 8;
    const int q_sx  = (q_row & 7) << 4;
    const int q_cb  = ((lane >> 4) & 1) * 16;
    const int k_rl  = (lane & 7) + ((lane >> 4) & 1) * 8;
    const int k_cb  = ((lane >> 3) & 1) * 16;
    const int v_rl  = (lane & 7) + ((lane >> 3) & 1) * 8;
    const int v_cb  = ((lane >> 4) & 1) * 16;

    float lacc[4] = {0.0f, 0.0f, 0.0f, 0.0f};
    float acc[8][4];
    #pragma unroll
    for (int e = 0; e < 8; ++e)
        #pragma unroll
        for (int r = 0; r < 4; ++r) acc[e][r] = 0.0f;

    const int NT = S_LEN / 64;

    asm volatile("cp.async.wait_group 2;\n" ::: "memory");
    __syncthreads();

    uint32_t qf[4][4];
    #pragma unroll
    for (int kd = 0; kd < 4; ++kd)
        ldm_x4(qf[kd][0], qf[kd][1], qf[kd][2], qf[kd][3],
               sQ + q_row * 128 + ((kd * 32 + q_cb) ^ q_sx));

    for (int t = 0; t < NT; ++t) {
        if (t > 0) {
            if (t < NT - 2)       asm volatile("cp.async.wait_group 2;\n" ::: "memory");
            else if (t == NT - 2) asm volatile("cp.async.wait_group 1;\n" ::: "memory");
            else                  asm volatile("cp.async.wait_group 0;\n" ::: "memory");
            __syncthreads();
        }

        if (t + 3 < NT) ldKV(t + 3);

        const uint32_t kb = sKV + (t & 3) * 16384;
        const uint32_t vb = kb + 8192;

        #pragma unroll
        for (int j = 0; j < 4; ++j) {
            float s0[4], s1[4];
            #pragma unroll
            for (int r = 0; r < 4; ++r) { s0[r] = 0.0f; s1[r] = 0.0f; }

            const int krow = j * 16 + k_rl;
            const int ksx  = (krow & 7) << 4;
            #pragma unroll
            for (int kd = 0; kd < 4; ++kd) {
                uint32_t k0, k1, k2, k3;
                ldm_x4(k0, k1, k2, k3,
                       kb + krow * 128 + ((kd * 32 + k_cb) ^ ksx));
                mma_f16(s0[0], s0[1], s0[2], s0[3],
                        qf[kd][0], qf[kd][1], qf[kd][2], qf[kd][3], k0, k1);
                mma_f16(s1[0], s1[1], s1[2], s1[3],
                        qf[kd][0], qf[kd][1], qf[kd][2], qf[kd][3], k2, k3);
            }

            uint32_t ap[4];
            ap[0] = ex2h2(packh2(s0[0], s0[1]));
            ap[1] = ex2h2(packh2(s0[2], s0[3]));
            ap[2] = ex2h2(packh2(s1[0], s1[1]));
            ap[3] = ex2h2(packh2(s1[2], s1[3]));

            mma_f16(lacc[0], lacc[1], lacc[2], lacc[3],
                    ap[0], ap[1], ap[2], ap[3], ONES_H2, ONES_H2);
            const int vrow = j * 16 + v_rl;
            const int vsx  = (vrow & 7) << 4;
            #pragma unroll
            for (int e = 0; e < 4; ++e) {
                uint32_t v0, v1, v2, v3;
                ldm_x4t(v0, v1, v2, v3,
                        vb + vrow * 128 + ((e * 32 + v_cb) ^ vsx));
                mma_f16(acc[2*e][0], acc[2*e][1], acc[2*e][2], acc[2*e][3],
                        ap[0], ap[1], ap[2], ap[3], v0, v1);
                mma_f16(acc[2*e+1][0], acc[2*e+1][1], acc[2*e+1][2], acc[2*e+1][3],
                        ap[0], ap[1], ap[2], ap[3], v2, v3);
            }
        }
    }

    const float inv0 = 1.0f / lacc[0];
    const float inv1 = 1.0f / lacc[2];
    const size_t row0 = rowbase + qbase + wr + (lane >> 2);
    const size_t row1 = row0 + 8;
    const int cb = h * HD + 2 * (lane & 3);
    #pragma unroll
    for (int e = 0; e < 8; ++e) {
        const int c = cb + e * 8;
        *(uint32_t*)(O + row0 * EMB + c) = packh2(acc[e][0] * inv0, acc[e][1] * inv0);
        *(uint32_t*)(O + row1 * EMB + c) = packh2(acc[e][2] * inv1, acc[e][3] * inv1);
    }
}

// ======================= fused mega-kernel ==================================
// bids [0,1536): QKV GEMM (m-major: batch 0 first). release qkv_done[b][nblk].
// bids [1536,2560): attention (waits 3 col-blocks of its batch). release attn_done.
// bids [2560,3072): O-proj (waits its rowblock's 16 heads).
// HW dispatches bids in order => producers always precede consumers => no deadlock.
#define G1_BLKS  1536
#define ATT_BLKS 1024

__global__ __launch_bounds__(256, 2)
void fused_mha(const __half* __restrict__ xh, const __half* __restrict__ wqkv,
               const float* __restrict__ bqkv,
               __half* __restrict__ qkvh, __half* __restrict__ oh,
               const __half* __restrict__ wo, const float* __restrict__ bo,
               float* __restrict__ out) {
    extern __shared__ char smem[];
    const int bid = blockIdx.x;
    const int tid = threadIdx.x;

    if (bid < G1_BLKS) {
        const int nblk = bid % 24;
        const int mblk = bid / 24;
        gemm_body(xh, wqkv, bqkv, nullptr, qkvh, QKV_LD,
                  mblk * 128, nblk * 128, smem);
        __threadfence();
        __syncthreads();
        if (tid == 0)
            atomicAdd(&g_qkv_done[(mblk >> 4) * 24 + nblk], 1);
    } else if (bid < G1_BLKS + ATT_BLKS) {
        const int idx = bid - G1_BLKS;
        const int qtile = idx & 15;
        const int bh = idx >> 4;
        const int b = bh >> 4, h = bh & 15;
        if (tid == 0) {
            wait_cnt16(&g_qkv_done[b * 24 + (h >> 1)]);          // Q cols
            wait_cnt16(&g_qkv_done[b * 24 + 8 + (h >> 1)]);      // K cols
            wait_cnt16(&g_qkv_done[b * 24 + 16 + (h >> 1)]);     // V cols
            __threadfence();
        }
        __syncthreads();
        attn_body(qkvh, oh, qtile, bh, smem);
        __threadfence();
        __syncthreads();
        if (tid == 0)
            atomicAdd(&g_attn_done[b * 16 + qtile], 1);
    } else {
        const int idx = bid - G1_BLKS - ATT_BLKS;
        const int nblk = idx & 7;
        const int mblk = idx >> 3;
        if (tid == 0) {
            wait_cnt16(&g_attn_done[mblk]);
            __threadfence();
        }
        __syncthreads();
        gemm_body(oh, wo, bo, out, nullptr, EMB,
                  mblk * 128, nblk * 128, smem);
    }
}

// ======================= launch =============================================
extern "C" void kernel_launch(void* const* d_in, const int* in_sizes, int n_in,
                              void* d_out, int out_size) {
    const float* x  = (const float*)d_in[0];
    const float* Wq = (const float*)d_in[1];
    const float* bq = (const float*)d_in[2];
    const float* Wk = (const float*)d_in[3];
    const float* bk = (const float*)d_in[4];
    const float* Wv = (const float*)d_in[5];
    const float* bv = (const float*)d_in[6];
    const float* Wo = (const float*)d_in[7];
    const float* bo = (const float*)d_in[8];
    float* out = (float*)d_out;

    __half *xh, *wqh, *woh, *oh, *qkvh;
    float *bqkv;
    cudaGetSymbolAddress((void**)&xh, g_xh);
    cudaGetSymbolAddress((void**)&wqh, g_WTqkv_h);
    cudaGetSymbolAddress((void**)&woh, g_WTo_h);
    cudaGetSymbolAddress((void**)&oh, g_Oh);
    cudaGetSymbolAddress((void**)&qkvh, g_QKVh);
    cudaGetSymbolAddress((void**)&bqkv, g_biasqkv);

    cudaFuncSetAttribute(fused_mha, cudaFuncAttributeMaxDynamicSharedMemorySize,
                         GEMM_SMEM_BYTES);

    // preprocessing (also zeroes dependency counters)
    prep_all<<<PREP_GRID, 256>>>(x, Wq, Wk, Wv, Wo, bq, bk, bv,
                                 xh, wqh, woh, bqkv);

    // the whole MHA as one kernel with flag-ordered roles
    fused_mha<<<G1_BLKS + ATT_BLKS + 512, 256, GEMM_SMEM_BYTES>>>(
        xh, wqh, bqkv, qkvh, oh, woh, bo, out);
}